// round 2
// baseline (speedup 1.0000x reference)
#include <cuda_runtime.h>
#include <cuda_bf16.h>

// ---------------------------------------------------------------------------
// SRF layer: grouped conv where filters are Gaussian-Hermite (order 2) bases
// mixed by learned alphas. 5 groups, 4 in-ch -> 8 out-ch per group.
// Filters are separable: B[n] = outer(d_i, d_j), i+j<=2.
//   1) precompute kernel: sigma -> d0/d1/d2 taps (lane-duplicated for f32x2)
//      + lane-duplicated alphas, into __device__ globals.
//   2) conv kernel: per-thread column-pair, horizontal conv -> basis mix ->
//      vertical scatter into a T-deep accumulator ring, all in packed f32x2.
//   Head rows (i < 2F) guard the scatter with k <= i to avoid ghost terms
//   (contributions belonging to the strip above) polluting reused ring slots.
// ---------------------------------------------------------------------------

#define H 384
#define W 384
#define B 16
#define INC 20
#define OUTC 40
#define NG 5          // groups
#define ICG 4         // in channels / group
#define OCG 8         // out channels / group
#define NB 6          // basis count
#define SH 96         // strip height (384/96 = 4 strips)

__device__ float2 g_dp[NG][3][5];            // duplicated taps [scale][deriv][tap]
__device__ float2 g_alpha[NG][NB][ICG][OCG]; // duplicated alphas

// ---- packed f32x2 helpers -------------------------------------------------
__device__ __forceinline__ unsigned long long pk2(float a, float b) {
    unsigned long long r;
    asm("mov.b64 %0, {%1, %2};" : "=l"(r) : "f"(a), "f"(b));
    return r;
}
__device__ __forceinline__ unsigned long long fma2(unsigned long long a,
                                                   unsigned long long b,
                                                   unsigned long long c) {
    unsigned long long d;
    asm("fma.rn.f32x2 %0, %1, %2, %3;" : "=l"(d) : "l"(a), "l"(b), "l"(c));
    return d;
}
__device__ __forceinline__ void unpk2(unsigned long long v, float& lo, float& hi) {
    asm("mov.b64 {%0, %1}, %2;" : "=f"(lo), "=f"(hi) : "l"(v));
}

// ---- precompute: taps + duplicated alphas ---------------------------------
__global__ void srf_precompute(const float* __restrict__ alphas,
                               const float* __restrict__ scales) {
    int tid = threadIdx.x;
    if (tid < NG) {
        const int FSarr[5] = {1, 1, 1, 2, 2};
        int s = tid;
        float mn = 0.2f * s, mx = mn + 0.2f;
        float sigma = (mx - mn) * 0.5f * tanhf(scales[s]) + (mn + mx) * 0.5f;
        int F = FSarr[s];
        int T = 2 * F + 1;
        float g[5];
        float sum = 0.f;
        for (int k = 0; k < T; ++k) {
            float x = (float)(k - F);
            g[k] = expf(-(x * x) / (2.f * sigma * sigma));
            sum += g[k];
        }
        float inv = 1.f / sum;
        float c1 = -1.f / (sigma * 1.41421356237309515f);
        for (int k = 0; k < 5; ++k) {
            float d0 = 0.f, d1 = 0.f, d2 = 0.f;
            if (k < T) {
                float x = (float)(k - F);
                float gg = g[k] * inv;
                float u = x / (sigma * 1.41421356237309515f);
                d0 = gg;
                d1 = c1 * (2.f * u) * gg;
                d2 = (c1 * c1) * (4.f * u * u - 2.f) * gg;
            }
            g_dp[s][0][k] = make_float2(d0, d0);
            g_dp[s][1][k] = make_float2(d1, d1);
            g_dp[s][2][k] = make_float2(d2, d2);
        }
    }
    // alphas: [5][6][4][8] contiguous
    for (int idx = tid; idx < NG * NB * ICG * OCG; idx += blockDim.x) {
        float a = alphas[idx];
        ((float2*)g_alpha)[idx] = make_float2(a, a);
    }
}

// ---- one row step ---------------------------------------------------------
template <int T, bool HEAD>
__device__ __forceinline__ void srf_row_step(
    int i, int u, int y0, int x0,
    const bool (&xv)[T + 1],
    const float* __restrict__ inb, float* __restrict__ outb,
    const unsigned long long (&dp)[3][T],
    const float2 (*__restrict__ sA)[ICG][OCG],
    unsigned long long (&acc)[T][OCG]) {
    constexpr int F = T / 2;
    const int IV[NB] = {0, 0, 0, 1, 1, 2};
    const int JH[NB] = {0, 1, 2, 0, 1, 0};

    int r = y0 - F + i;
    bool rv = (r >= 0 && r < H);

    // ---- horizontal pass: h[ch][jh] (packed pair) ----
    unsigned long long hh[ICG][3];
#pragma unroll
    for (int ch = 0; ch < ICG; ++ch) {
        const float* row = inb + ((size_t)ch * H + (size_t)(rv ? r : 0)) * W;
        float w[T + 1];
#pragma unroll
        for (int j = 0; j <= T; ++j) {
            int xx = x0 - F + j;
            w[j] = (rv && xv[j]) ? __ldg(row + xx) : 0.f;
        }
        unsigned long long pkv[T];
#pragma unroll
        for (int k = 0; k < T; ++k) pkv[k] = pk2(w[k], w[k + 1]);
#pragma unroll
        for (int jh = 0; jh < 3; ++jh) {
            unsigned long long acc_h = 0ULL;
#pragma unroll
            for (int k = 0; k < T; ++k)
                acc_h = fma2(dp[jh][k], pkv[k], acc_h);
            hh[ch][jh] = acc_h;
        }
    }

    // ---- basis/channel mixing: m[o][iv] ----
    unsigned long long m[OCG][3];
#pragma unroll
    for (int o = 0; o < OCG; ++o)
#pragma unroll
        for (int v = 0; v < 3; ++v) m[o][v] = 0ULL;
#pragma unroll
    for (int n = 0; n < NB; ++n) {
        const int iv = IV[n], jh = JH[n];
#pragma unroll
        for (int ch = 0; ch < ICG; ++ch) {
            unsigned long long t = hh[ch][jh];
            const unsigned long long* arow =
                (const unsigned long long*)&sA[n][ch][0];
#pragma unroll
            for (int o = 0; o < OCG; ++o)
                m[o][iv] = fma2(arow[o], t, m[o][iv]);
        }
    }

    // ---- vertical scatter into accumulator ring ----
    // HEAD guard: terms with k > i belong to output rows above this strip
    // (y = y0 + i - k < y0); emitting them would pollute ring slots reused
    // for outputs y + T. Only possible while i < 2F, i.e., the peeled block.
#pragma unroll
    for (int k = 0; k < T; ++k) {
        if (HEAD && k > i) continue;
        const int s = ((u - k + 2 * F) % T + T) % T;
#pragma unroll
        for (int o = 0; o < OCG; ++o) {
            unsigned long long a = acc[s][o];
            a = fma2(dp[0][k], m[o][0], a);
            a = fma2(dp[1][k], m[o][1], a);
            a = fma2(dp[2][k], m[o][2], a);
            acc[s][o] = a;
        }
    }

    // ---- store completed row (ring slot u) ----
    if (i >= 2 * F && i < SH + 2 * F) {
        int y = y0 + i - 2 * F;
#pragma unroll
        for (int o = 0; o < OCG; ++o) {
            float lo, hi;
            unpk2(acc[u][o], lo, hi);
            *(float2*)(outb + ((size_t)o * H + y) * W + x0) = make_float2(lo, hi);
            acc[u][o] = 0ULL;
        }
    }
}

// ---- conv kernel ----------------------------------------------------------
// grid: (xblocks=3, strips=4, nbatch*ngroups). 64 threads = 64 column pairs.
template <int T>
__global__ void __launch_bounds__(64)
srf_conv(const float* __restrict__ in, float* __restrict__ out,
         int gBase, int ng) {
    constexpr int F = T / 2;
    constexpr int ITER = ((SH + 2 * F + T - 1) / T) * T;

    int gi = blockIdx.z % ng;
    int b  = blockIdx.z / ng;
    int g  = gBase + gi;

    int x0 = 2 * (blockIdx.x * 64 + threadIdx.x);
    int y0 = blockIdx.y * SH;

    const float* inb = in + ((size_t)b * INC + (size_t)g * ICG) * (H * W);
    float* outb      = out + ((size_t)b * OUTC + (size_t)g * OCG) * (H * W);

    __shared__ float2 sA[NB][ICG][OCG];
    {
        const float2* src = (const float2*)g_alpha[g];
        for (int idx = threadIdx.x; idx < NB * ICG * OCG; idx += 64)
            ((float2*)sA)[idx] = src[idx];
    }
    unsigned long long dp[3][T];
#pragma unroll
    for (int d = 0; d < 3; ++d)
#pragma unroll
        for (int k = 0; k < T; ++k)
            dp[d][k] = *(const unsigned long long*)&g_dp[g][d][k];
    __syncthreads();

    // column-validity masks for the T+1 wide input window (shared by all rows)
    bool xv[T + 1];
#pragma unroll
    for (int j = 0; j <= T; ++j) {
        int xx = x0 - F + j;
        xv[j] = (xx >= 0 && xx < W);
    }

    unsigned long long acc[T][OCG];
#pragma unroll
    for (int s = 0; s < T; ++s)
#pragma unroll
        for (int o = 0; o < OCG; ++o) acc[s][o] = 0ULL;

    // peeled head block: guard scatter against ghost terms (k > i)
#pragma unroll
    for (int u = 0; u < T; ++u)
        srf_row_step<T, true>(u, u, y0, x0, xv, inb, outb, dp, sA, acc);

    // steady state
    for (int ib = T; ib < ITER; ib += T) {
#pragma unroll
        for (int u = 0; u < T; ++u)
            srf_row_step<T, false>(ib + u, u, y0, x0, xv, inb, outb, dp, sA, acc);
    }
}

extern "C" void kernel_launch(void* const* d_in, const int* in_sizes, int n_in,
                              void* d_out, int out_size) {
    const float* data   = (const float*)d_in[0];
    const float* alphas = (const float*)d_in[1];
    const float* scales = (const float*)d_in[2];
    float* out = (float*)d_out;

    srf_precompute<<<1, 256>>>(alphas, scales);

    dim3 blk(64, 1, 1);
    dim3 gridA(3, H / SH, B * 3);  // groups 0..2, taps=3
    dim3 gridB(3, H / SH, B * 2);  // groups 3..4, taps=5
    srf_conv<3><<<gridA, blk>>>(data, out, 0, 3);
    srf_conv<5><<<gridB, blk>>>(data, out, 3, 2);
}